// round 2
// baseline (speedup 1.0000x reference)
#include <cuda_runtime.h>

#define N_NODES 10000
#define N_EDGES 160000
#define TE 32                    // edges per block in the edge kernel

#define INV_SQRT_MUL 0.08838834764831845f   // 1/sqrt(128)
#define INV_SQRT3    0.57735026918962576f
#define OUT_SCALE    0.00390625f            // (1/sqrt(256)) / 16

// ---------------------------------------------------------------------------
// Scratch (device globals: allocation-free)
// ---------------------------------------------------------------------------
__device__ float g_ns [N_NODES * 128];   // node_scalars
__device__ float g_su [N_NODES * 128];   // s_up
__device__ float g_vup[N_NODES * 384];   // v_up, layout [n][w][i] (i fastest)
__device__ float g_msg[N_NODES * 1024];  // segment-sum accumulator

static __device__ __forceinline__ float silu(float x) {
    return x / (1.0f + __expf(-x));
}

static __device__ __forceinline__ void red_add_v4(float* addr, float a, float b,
                                                  float c, float d) {
    asm volatile("red.global.add.v4.f32 [%0], {%1, %2, %3, %4};"
                 :: "l"(addr), "f"(a), "f"(b), "f"(c), "f"(d) : "memory");
}

// ---------------------------------------------------------------------------
// Kernel 0: zero the message accumulator (2.56M float4, one per thread)
// ---------------------------------------------------------------------------
__global__ void k_zero() {
    int i = blockIdx.x * blockDim.x + threadIdx.x;
    ((float4*)g_msg)[i] = make_float4(0.f, 0.f, 0.f, 0.f);
}

// ---------------------------------------------------------------------------
// Kernel 1: per-node precompute
//   node_scalars = s_in @ W_scalar * inv
//   s_up         = s_in @ W_up0   * inv
//   v_up[n,w,i]  = sum_u v_in[n,u,i] * W_up1[u,w] * inv
// One block per node, 128 threads; thread t owns output column w = t.
// ---------------------------------------------------------------------------
__global__ void __launch_bounds__(128) k_node(
    const float* __restrict__ nf,
    const float* __restrict__ Ws,
    const float* __restrict__ Wu0,
    const float* __restrict__ Wu1)
{
    __shared__ float s_sh[128];
    __shared__ float v_sh[384];
    const int n = blockIdx.x;
    const int t = threadIdx.x;

    s_sh[t] = nf[n * 512 + t];
    v_sh[t]       = nf[n * 512 + 128 + t];
    v_sh[t + 128] = nf[n * 512 + 256 + t];
    v_sh[t + 256] = nf[n * 512 + 384 + t];
    __syncthreads();

    float a0 = 0.f, a1 = 0.f, av0 = 0.f, av1 = 0.f, av2 = 0.f;
#pragma unroll 4
    for (int u = 0; u < 128; ++u) {
        float s = s_sh[u];
        a0 += s * Ws [u * 128 + t];
        a1 += s * Wu0[u * 128 + t];
        float w = Wu1[u * 128 + t];
        av0 += v_sh[u * 3 + 0] * w;
        av1 += v_sh[u * 3 + 1] * w;
        av2 += v_sh[u * 3 + 2] * w;
    }
    g_ns[n * 128 + t] = a0 * INV_SQRT_MUL;
    g_su[n * 128 + t] = a1 * INV_SQRT_MUL;
    g_vup[n * 384 + t * 3 + 0] = av0 * INV_SQRT_MUL;
    g_vup[n * 384 + t * 3 + 1] = av1 * INV_SQRT_MUL;
    g_vup[n * 384 + t * 3 + 2] = av2 * INV_SQRT_MUL;
}

// ---------------------------------------------------------------------------
// Kernel 2: per-edge MLP (265 -> 128 -> 128 -> 512) + message construction
//           + atomic segment-sum into g_msg.
// 512 threads, TE=32 edges per block. Thread t: edge e = t>>4, column group
// g = t&15 owning output columns c0 = 8g .. 8g+7.
// smem: x_sm[e][0:265] = mlp_in; after layer1, h1 overwrites cols 0:128;
//       after layer2, h2 goes into cols 128:256.
// ---------------------------------------------------------------------------
__global__ void __launch_bounds__(512) k_edge(
    const float* __restrict__ edge_attrs,
    const float* __restrict__ edge_feats,
    const float* __restrict__ lengths,
    const int*   __restrict__ edge_index,
    const float* __restrict__ W1, const float* __restrict__ b1,
    const float* __restrict__ W2, const float* __restrict__ b2,
    const float* __restrict__ W3)
{
    __shared__ __align__(16) float x_sm[TE][272];

    const int t  = threadIdx.x;
    const int e  = t >> 4;           // 0..31 local edge
    const int g  = t & 15;           // 0..15 column group
    const int c0 = g * 8;
    const int eg = blockIdx.x * TE + e;

    const int snd = edge_index[eg];
    const int rcv = edge_index[N_EDGES + eg];

    // ---- stage mlp_in ----
    {
        const float4* ps = (const float4*)(g_ns + snd * 128 + c0);
        const float4* pr = (const float4*)(g_ns + rcv * 128 + c0);
        *(float4*)&x_sm[e][c0]       = ps[0];
        *(float4*)&x_sm[e][c0 + 4]   = ps[1];
        *(float4*)&x_sm[e][128 + c0]     = pr[0];
        *(float4*)&x_sm[e][128 + c0 + 4] = pr[1];
        if (g == 0) {
            const float4* pf = (const float4*)(edge_feats + eg * 8);
            *(float4*)&x_sm[e][256] = pf[0];
            *(float4*)&x_sm[e][260] = pf[1];
            x_sm[e][264] = lengths[eg];
        }
    }
    __syncthreads();

    // ---- layer 1: 265 -> 128, silu ----
    float acc[8];
    {
        float4 ba = *(const float4*)(b1 + c0);
        float4 bb = *(const float4*)(b1 + c0 + 4);
        acc[0]=ba.x; acc[1]=ba.y; acc[2]=ba.z; acc[3]=ba.w;
        acc[4]=bb.x; acc[5]=bb.y; acc[6]=bb.z; acc[7]=bb.w;
#pragma unroll 4
        for (int k = 0; k < 265; ++k) {
            float x = x_sm[e][k];
            float4 wa = *(const float4*)(W1 + k * 128 + c0);
            float4 wb = *(const float4*)(W1 + k * 128 + c0 + 4);
            acc[0] += x * wa.x; acc[1] += x * wa.y;
            acc[2] += x * wa.z; acc[3] += x * wa.w;
            acc[4] += x * wb.x; acc[5] += x * wb.y;
            acc[6] += x * wb.z; acc[7] += x * wb.w;
        }
    }
    __syncthreads();                       // all reads of x_sm done
#pragma unroll
    for (int j = 0; j < 8; ++j) x_sm[e][c0 + j] = silu(acc[j]);  // h1 -> cols 0:128
    __syncthreads();

    // ---- layer 2: 128 -> 128, silu ----
    {
        float4 ba = *(const float4*)(b2 + c0);
        float4 bb = *(const float4*)(b2 + c0 + 4);
        acc[0]=ba.x; acc[1]=ba.y; acc[2]=ba.z; acc[3]=ba.w;
        acc[4]=bb.x; acc[5]=bb.y; acc[6]=bb.z; acc[7]=bb.w;
#pragma unroll 4
        for (int k = 0; k < 128; ++k) {
            float x = x_sm[e][k];
            float4 wa = *(const float4*)(W2 + k * 128 + c0);
            float4 wb = *(const float4*)(W2 + k * 128 + c0 + 4);
            acc[0] += x * wa.x; acc[1] += x * wa.y;
            acc[2] += x * wa.z; acc[3] += x * wa.w;
            acc[4] += x * wb.x; acc[5] += x * wb.y;
            acc[6] += x * wb.z; acc[7] += x * wb.w;
        }
    }
    __syncthreads();                       // all reads of h1 done
#pragma unroll
    for (int j = 0; j < 8; ++j) x_sm[e][128 + c0 + j] = silu(acc[j]);  // h2 -> cols 128:256
    __syncthreads();

    // ---- layer 3: 128 -> 512 (tpw = [w0 w1 w2 w3], this thread owns
    //      columns c0..c0+7 of each 128-wide segment) ----
    float a0[8], a1[8], a2[8], a3[8];
#pragma unroll
    for (int j = 0; j < 8; ++j) { a0[j]=0.f; a1[j]=0.f; a2[j]=0.f; a3[j]=0.f; }
#pragma unroll 2
    for (int k = 0; k < 128; ++k) {
        float x = x_sm[e][128 + k];
        const float* wr = W3 + k * 512;
        float4 s0a = *(const float4*)(wr + c0);
        float4 s0b = *(const float4*)(wr + c0 + 4);
        float4 s1a = *(const float4*)(wr + 128 + c0);
        float4 s1b = *(const float4*)(wr + 128 + c0 + 4);
        float4 s2a = *(const float4*)(wr + 256 + c0);
        float4 s2b = *(const float4*)(wr + 256 + c0 + 4);
        float4 s3a = *(const float4*)(wr + 384 + c0);
        float4 s3b = *(const float4*)(wr + 384 + c0 + 4);
        a0[0]+=x*s0a.x; a0[1]+=x*s0a.y; a0[2]+=x*s0a.z; a0[3]+=x*s0a.w;
        a0[4]+=x*s0b.x; a0[5]+=x*s0b.y; a0[6]+=x*s0b.z; a0[7]+=x*s0b.w;
        a1[0]+=x*s1a.x; a1[1]+=x*s1a.y; a1[2]+=x*s1a.z; a1[3]+=x*s1a.w;
        a1[4]+=x*s1b.x; a1[5]+=x*s1b.y; a1[6]+=x*s1b.z; a1[7]+=x*s1b.w;
        a2[0]+=x*s2a.x; a2[1]+=x*s2a.y; a2[2]+=x*s2a.z; a2[3]+=x*s2a.w;
        a2[4]+=x*s2b.x; a2[5]+=x*s2b.y; a2[6]+=x*s2b.z; a2[7]+=x*s2b.w;
        a3[0]+=x*s3a.x; a3[1]+=x*s3a.y; a3[2]+=x*s3a.z; a3[3]+=x*s3a.w;
        a3[4]+=x*s3b.x; a3[5]+=x*s3b.y; a3[6]+=x*s3b.z; a3[7]+=x*s3b.w;
    }

    // ---- message construction + atomic scatter ----
    float4 ea = *(const float4*)(edge_attrs + eg * 4);
    const float y0 = ea.x, y1x = ea.y, y1y = ea.z, y1z = ea.w;

    float se[8];
    {
        float4 sa = *(const float4*)(g_su + snd * 128 + c0);
        float4 sb = *(const float4*)(g_su + snd * 128 + c0 + 4);
        se[0]=sa.x; se[1]=sa.y; se[2]=sa.z; se[3]=sa.w;
        se[4]=sb.x; se[5]=sb.y; se[6]=sb.z; se[7]=sb.w;
    }
    float vb[24];
    {
        const float4* pv = (const float4*)(g_vup + snd * 384 + c0 * 3);
#pragma unroll
        for (int q = 0; q < 6; ++q) {
            float4 v = pv[q];
            vb[q*4+0]=v.x; vb[q*4+1]=v.y; vb[q*4+2]=v.z; vb[q*4+3]=v.w;
        }
    }

    float* base = g_msg + rcv * 1024;
    float m[24];

    // m0a = w0 * se * y0             -> cols [0,128)
#pragma unroll
    for (int j = 0; j < 8; ++j) m[j] = a0[j] * se[j] * y0;
    red_add_v4(base + c0,     m[0], m[1], m[2], m[3]);
    red_add_v4(base + c0 + 4, m[4], m[5], m[6], m[7]);

    // m0b = w3 * (ve . y1) / sqrt(3) -> cols [128,256)
#pragma unroll
    for (int j = 0; j < 8; ++j) {
        float dot = vb[3*j] * y1x + vb[3*j+1] * y1y + vb[3*j+2] * y1z;
        m[j] = a3[j] * dot * INV_SQRT3;
    }
    red_add_v4(base + 128 + c0,     m[0], m[1], m[2], m[3]);
    red_add_v4(base + 128 + c0 + 4, m[4], m[5], m[6], m[7]);

    // m1a[c][i] = (w1*se)[c] * y1[i] -> cols [256 + 3c .. )
#pragma unroll
    for (int j = 0; j < 8; ++j) {
        float t1 = a1[j] * se[j];
        m[3*j+0] = t1 * y1x; m[3*j+1] = t1 * y1y; m[3*j+2] = t1 * y1z;
    }
    {
        float* p = base + 256 + c0 * 3;
#pragma unroll
        for (int q = 0; q < 6; ++q)
            red_add_v4(p + 4*q, m[4*q], m[4*q+1], m[4*q+2], m[4*q+3]);
    }

    // m1b[c][i] = (w2*y0)[c] * ve[c][i] -> cols [640 + 3c .. )
#pragma unroll
    for (int j = 0; j < 8; ++j) {
        float t2 = a2[j] * y0;
        m[3*j+0] = t2 * vb[3*j+0]; m[3*j+1] = t2 * vb[3*j+1]; m[3*j+2] = t2 * vb[3*j+2];
    }
    {
        float* p = base + 640 + c0 * 3;
#pragma unroll
        for (int q = 0; q < 6; ++q)
            red_add_v4(p + 4*q, m[4*q], m[4*q+1], m[4*q+2], m[4*q+3]);
    }
}

// ---------------------------------------------------------------------------
// Kernel 3: node output
//   out[n,w,0]    = (ms  @ W_out0)[w] * OUT_SCALE       (ms = msg[:, :256])
//   out[n,w,1+i]  = (sum_u mv[n,u,i] W_out1[u,w]) * OUT_SCALE
// One block per node, 128 threads, thread w = t.
// ---------------------------------------------------------------------------
__global__ void __launch_bounds__(128) k_out(
    const float* __restrict__ W0,
    const float* __restrict__ W1o,
    float* __restrict__ out)
{
    __shared__ __align__(16) float m_sm[1024];
    const int n = blockIdx.x;
    const int t = threadIdx.x;

    const float4* src = (const float4*)(g_msg + n * 1024);
    ((float4*)m_sm)[t]       = src[t];
    ((float4*)m_sm)[t + 128] = src[t + 128];
    __syncthreads();

    float a0 = 0.f, v0 = 0.f, v1 = 0.f, v2 = 0.f;
#pragma unroll 4
    for (int u = 0; u < 256; ++u) {
        a0 += m_sm[u] * W0[u * 128 + t];
        float w = W1o[u * 128 + t];
        v0 += m_sm[256 + u * 3 + 0] * w;
        v1 += m_sm[256 + u * 3 + 1] * w;
        v2 += m_sm[256 + u * 3 + 2] * w;
    }
    *(float4*)(out + n * 512 + t * 4) =
        make_float4(a0 * OUT_SCALE, v0 * OUT_SCALE, v1 * OUT_SCALE, v2 * OUT_SCALE);
}

// ---------------------------------------------------------------------------
// Launch
// ---------------------------------------------------------------------------
extern "C" void kernel_launch(void* const* d_in, const int* in_sizes, int n_in,
                              void* d_out, int out_size)
{
    const float* node_feats = (const float*)d_in[0];
    const float* edge_attrs = (const float*)d_in[1];
    const float* edge_feats = (const float*)d_in[2];
    const float* lengths    = (const float*)d_in[3];
    const int*   edge_index = (const int*)  d_in[4];
    const float* W_scalar   = (const float*)d_in[5];
    const float* W_up0      = (const float*)d_in[6];
    const float* W_up1      = (const float*)d_in[7];
    const float* W_mlp1     = (const float*)d_in[8];
    const float* b_mlp1     = (const float*)d_in[9];
    const float* W_mlp2     = (const float*)d_in[10];
    const float* b_mlp2     = (const float*)d_in[11];
    const float* W_mlp3     = (const float*)d_in[12];
    const float* W_out0     = (const float*)d_in[13];
    const float* W_out1     = (const float*)d_in[14];
    float* out = (float*)d_out;

    k_zero<<<5000, 512>>>();                      // 2.56M float4 == 10.24M floats
    k_node<<<N_NODES, 128>>>(node_feats, W_scalar, W_up0, W_up1);
    k_edge<<<N_EDGES / TE, 512>>>(edge_attrs, edge_feats, lengths, edge_index,
                                  W_mlp1, b_mlp1, W_mlp2, b_mlp2, W_mlp3);
    k_out<<<N_NODES, 128>>>(W_out0, W_out1, out);
}

// round 3
// speedup vs baseline: 3.0685x; 3.0685x over previous
#include <cuda_runtime.h>

#define N_NODES 10000
#define N_EDGES 160000
#define TE 32                    // edges per block in the edge kernel

#define INV_SQRT_MUL 0.08838834764831845f   // 1/sqrt(128)
#define INV_SQRT3    0.57735026918962576f
#define OUT_SCALE    0.00390625f            // (1/sqrt(256)) / 16

// ---------------------------------------------------------------------------
// Scratch (device globals: allocation-free)
// ---------------------------------------------------------------------------
__device__ float g_ns [N_NODES * 128];   // node_scalars
__device__ float g_su [N_NODES * 128];   // s_up
__device__ float g_vup[N_NODES * 384];   // v_up, layout [n][w][i] (i fastest)
__device__ float g_msg[N_NODES * 1024];  // segment-sum accumulator

static __device__ __forceinline__ float silu(float x) {
    return x / (1.0f + __expf(-x));
}

static __device__ __forceinline__ void red_add_v4(float* addr, float a, float b,
                                                  float c, float d) {
    asm volatile("red.global.add.v4.f32 [%0], {%1, %2, %3, %4};"
                 :: "l"(addr), "f"(a), "f"(b), "f"(c), "f"(d) : "memory");
}

// ---------------------------------------------------------------------------
// Kernel 0: zero the message accumulator
// ---------------------------------------------------------------------------
__global__ void k_zero() {
    int i = blockIdx.x * blockDim.x + threadIdx.x;
    ((float4*)g_msg)[i] = make_float4(0.f, 0.f, 0.f, 0.f);
}

// ---------------------------------------------------------------------------
// Kernel 1: per-node precompute, 4 nodes per block (weight reuse x4)
// 128 threads; thread t owns output column w = t for all 4 nodes.
// ---------------------------------------------------------------------------
__global__ void __launch_bounds__(128) k_node(
    const float* __restrict__ nf,
    const float* __restrict__ Ws,
    const float* __restrict__ Wu0,
    const float* __restrict__ Wu1)
{
    __shared__ float s_sh[4][128];
    __shared__ float v_sh[4][384];
    const int n0 = blockIdx.x * 4;
    const int t = threadIdx.x;

#pragma unroll
    for (int nn = 0; nn < 4; ++nn) {
        const float* src = nf + (n0 + nn) * 512;
        s_sh[nn][t]       = src[t];
        v_sh[nn][t]       = src[128 + t];
        v_sh[nn][t + 128] = src[256 + t];
        v_sh[nn][t + 256] = src[384 + t];
    }
    __syncthreads();

    float a0[4], a1[4], av0[4], av1[4], av2[4];
#pragma unroll
    for (int nn = 0; nn < 4; ++nn) { a0[nn]=0.f; a1[nn]=0.f; av0[nn]=0.f; av1[nn]=0.f; av2[nn]=0.f; }

#pragma unroll 2
    for (int u = 0; u < 128; ++u) {
        float ws  = Ws [u * 128 + t];
        float wu0 = Wu0[u * 128 + t];
        float wu1 = Wu1[u * 128 + t];
#pragma unroll
        for (int nn = 0; nn < 4; ++nn) {
            float s = s_sh[nn][u];
            a0[nn] += s * ws;
            a1[nn] += s * wu0;
            av0[nn] += v_sh[nn][u * 3 + 0] * wu1;
            av1[nn] += v_sh[nn][u * 3 + 1] * wu1;
            av2[nn] += v_sh[nn][u * 3 + 2] * wu1;
        }
    }
#pragma unroll
    for (int nn = 0; nn < 4; ++nn) {
        int n = n0 + nn;
        g_ns[n * 128 + t] = a0[nn] * INV_SQRT_MUL;
        g_su[n * 128 + t] = a1[nn] * INV_SQRT_MUL;
        g_vup[n * 384 + t * 3 + 0] = av0[nn] * INV_SQRT_MUL;
        g_vup[n * 384 + t * 3 + 1] = av1[nn] * INV_SQRT_MUL;
        g_vup[n * 384 + t * 3 + 2] = av2[nn] * INV_SQRT_MUL;
    }
}

// ---------------------------------------------------------------------------
// Kernel 2: per-edge MLP (265 -> 128 -> 128 -> 512) + message + scatter.
// 256 threads, TE=32 edges per block.
// Thread t: cg = t & 31 -> owns cols c0 = 4*cg .. c0+3
//           et = t >> 5 -> owns edges et*4 .. et*4+3 (local)
// All 32 lanes of a warp share the same 4 edges -> x reads are smem broadcasts;
// weight float4 loads are coalesced 512B rows per warp, each amortized over
// 4 edges (16 FMA per 16B weight load in L1/2, 64 FMA per 64B in L3).
// ---------------------------------------------------------------------------
__global__ void __launch_bounds__(256, 2) k_edge(
    const float* __restrict__ edge_attrs,
    const float* __restrict__ edge_feats,
    const float* __restrict__ lengths,
    const int*   __restrict__ edge_index,
    const float* __restrict__ W1, const float* __restrict__ b1,
    const float* __restrict__ W2, const float* __restrict__ b2,
    const float* __restrict__ W3)
{
    __shared__ __align__(16) float x_sm[TE][272];

    const int t  = threadIdx.x;
    const int cg = t & 31;
    const int c0 = cg * 4;
    const int et = t >> 5;            // 0..7
    const int e0 = et * 4;            // first local edge of this thread
    const int ebase = blockIdx.x * TE;

    // ---- stage mlp_in: thread covers edge (t>>3), col chunk (t&7)*16 ----
    {
        const int e  = t >> 3;        // 0..31
        const int q  = t & 7;         // 0..7
        const int eg = ebase + e;
        const int snd = edge_index[eg];
        const int rcv = edge_index[N_EDGES + eg];
        const float4* ps = (const float4*)(g_ns + snd * 128 + q * 16);
        const float4* pr = (const float4*)(g_ns + rcv * 128 + q * 16);
#pragma unroll
        for (int i = 0; i < 4; ++i) {
            *(float4*)&x_sm[e][q * 16 + 4 * i]       = ps[i];
            *(float4*)&x_sm[e][128 + q * 16 + 4 * i] = pr[i];
        }
        if (q == 0) {
            const float4* pf = (const float4*)(edge_feats + eg * 8);
            *(float4*)&x_sm[e][256] = pf[0];
            *(float4*)&x_sm[e][260] = pf[1];
            x_sm[e][264] = lengths[eg];
        }
    }
    __syncthreads();

    // ---- layer 1: 265 -> 128, silu ----
    float acc[4][4];
    {
        float4 b = *(const float4*)(b1 + c0);
#pragma unroll
        for (int j = 0; j < 4; ++j) {
            acc[j][0]=b.x; acc[j][1]=b.y; acc[j][2]=b.z; acc[j][3]=b.w;
        }
#pragma unroll 4
        for (int k = 0; k < 265; ++k) {
            float4 w = *(const float4*)(W1 + k * 128 + c0);
#pragma unroll
            for (int j = 0; j < 4; ++j) {
                float x = x_sm[e0 + j][k];
                acc[j][0] += x * w.x; acc[j][1] += x * w.y;
                acc[j][2] += x * w.z; acc[j][3] += x * w.w;
            }
        }
    }
    __syncthreads();                 // all reads of x_sm done
#pragma unroll
    for (int j = 0; j < 4; ++j)
        *(float4*)&x_sm[e0 + j][c0] =
            make_float4(silu(acc[j][0]), silu(acc[j][1]), silu(acc[j][2]), silu(acc[j][3]));
    __syncthreads();

    // ---- layer 2: 128 -> 128, silu ----
    {
        float4 b = *(const float4*)(b2 + c0);
#pragma unroll
        for (int j = 0; j < 4; ++j) {
            acc[j][0]=b.x; acc[j][1]=b.y; acc[j][2]=b.z; acc[j][3]=b.w;
        }
#pragma unroll 4
        for (int k = 0; k < 128; ++k) {
            float4 w = *(const float4*)(W2 + k * 128 + c0);
#pragma unroll
            for (int j = 0; j < 4; ++j) {
                float x = x_sm[e0 + j][k];
                acc[j][0] += x * w.x; acc[j][1] += x * w.y;
                acc[j][2] += x * w.z; acc[j][3] += x * w.w;
            }
        }
    }
    __syncthreads();                 // all reads of h1 done
#pragma unroll
    for (int j = 0; j < 4; ++j)
        *(float4*)&x_sm[e0 + j][128 + c0] =
            make_float4(silu(acc[j][0]), silu(acc[j][1]), silu(acc[j][2]), silu(acc[j][3]));
    __syncthreads();

    // ---- layer 3: 128 -> 512 ----
    float a0[4][4], a1[4][4], a2[4][4], a3[4][4];
#pragma unroll
    for (int j = 0; j < 4; ++j)
#pragma unroll
        for (int i = 0; i < 4; ++i) { a0[j][i]=0.f; a1[j][i]=0.f; a2[j][i]=0.f; a3[j][i]=0.f; }

#pragma unroll 2
    for (int k = 0; k < 128; ++k) {
        const float* wr = W3 + k * 512;
        float4 w0 = *(const float4*)(wr + c0);
        float4 w1 = *(const float4*)(wr + 128 + c0);
        float4 w2 = *(const float4*)(wr + 256 + c0);
        float4 w3 = *(const float4*)(wr + 384 + c0);
#pragma unroll
        for (int j = 0; j < 4; ++j) {
            float x = x_sm[e0 + j][128 + k];
            a0[j][0] += x * w0.x; a0[j][1] += x * w0.y; a0[j][2] += x * w0.z; a0[j][3] += x * w0.w;
            a1[j][0] += x * w1.x; a1[j][1] += x * w1.y; a1[j][2] += x * w1.z; a1[j][3] += x * w1.w;
            a2[j][0] += x * w2.x; a2[j][1] += x * w2.y; a2[j][2] += x * w2.z; a2[j][3] += x * w2.w;
            a3[j][0] += x * w3.x; a3[j][1] += x * w3.y; a3[j][2] += x * w3.z; a3[j][3] += x * w3.w;
        }
    }

    // ---- message construction + atomic scatter (per owned edge) ----
    const int4 snd4 = *(const int4*)(edge_index + ebase + e0);
    const int4 rcv4 = *(const int4*)(edge_index + N_EDGES + ebase + e0);
    const int snds[4] = {snd4.x, snd4.y, snd4.z, snd4.w};
    const int rcvs[4] = {rcv4.x, rcv4.y, rcv4.z, rcv4.w};

#pragma unroll
    for (int j = 0; j < 4; ++j) {
        const int eg  = ebase + e0 + j;
        const int snd = snds[j];
        float4 ea = *(const float4*)(edge_attrs + eg * 4);
        const float y0 = ea.x, y1x = ea.y, y1y = ea.z, y1z = ea.w;

        float4 sev = *(const float4*)(g_su + snd * 128 + c0);
        float se[4] = {sev.x, sev.y, sev.z, sev.w};

        float f[12];
        {
            const float4* pv = (const float4*)(g_vup + snd * 384 + c0 * 3);
            float4 v0 = pv[0], v1 = pv[1], v2 = pv[2];
            f[0]=v0.x; f[1]=v0.y; f[2]=v0.z; f[3]=v0.w;
            f[4]=v1.x; f[5]=v1.y; f[6]=v1.z; f[7]=v1.w;
            f[8]=v2.x; f[9]=v2.y; f[10]=v2.z; f[11]=v2.w;
        }

        float* base = g_msg + rcvs[j] * 1024;

        // m0a = w0 * se * y0 -> cols [0,128)
        red_add_v4(base + c0,
                   a0[j][0]*se[0]*y0, a0[j][1]*se[1]*y0,
                   a0[j][2]*se[2]*y0, a0[j][3]*se[3]*y0);

        // m0b = w3 * (ve . y1) * inv_sqrt3 -> cols [128,256)
        {
            float m[4];
#pragma unroll
            for (int mcol = 0; mcol < 4; ++mcol) {
                float dot = f[3*mcol]*y1x + f[3*mcol+1]*y1y + f[3*mcol+2]*y1z;
                m[mcol] = a3[j][mcol] * dot * INV_SQRT3;
            }
            red_add_v4(base + 128 + c0, m[0], m[1], m[2], m[3]);
        }

        // m1a[c][i] = (w1*se)[c] * y1[i] -> cols [256 + 3c)
        {
            float o[12];
#pragma unroll
            for (int mcol = 0; mcol < 4; ++mcol) {
                float t1 = a1[j][mcol] * se[mcol];
                o[3*mcol+0] = t1 * y1x; o[3*mcol+1] = t1 * y1y; o[3*mcol+2] = t1 * y1z;
            }
            float* p = base + 256 + c0 * 3;
            red_add_v4(p,     o[0], o[1], o[2],  o[3]);
            red_add_v4(p + 4, o[4], o[5], o[6],  o[7]);
            red_add_v4(p + 8, o[8], o[9], o[10], o[11]);
        }

        // m1b[c][i] = (w2*y0)[c] * ve[c][i] -> cols [640 + 3c)
        {
            float o[12];
#pragma unroll
            for (int mcol = 0; mcol < 4; ++mcol) {
                float t2 = a2[j][mcol] * y0;
                o[3*mcol+0] = t2 * f[3*mcol+0];
                o[3*mcol+1] = t2 * f[3*mcol+1];
                o[3*mcol+2] = t2 * f[3*mcol+2];
            }
            float* p = base + 640 + c0 * 3;
            red_add_v4(p,     o[0], o[1], o[2],  o[3]);
            red_add_v4(p + 4, o[4], o[5], o[6],  o[7]);
            red_add_v4(p + 8, o[8], o[9], o[10], o[11]);
        }
    }
}

// ---------------------------------------------------------------------------
// Kernel 3: node output, 4 nodes per block (weight reuse x4)
// ---------------------------------------------------------------------------
__global__ void __launch_bounds__(128) k_out(
    const float* __restrict__ W0,
    const float* __restrict__ W1o,
    float* __restrict__ out)
{
    __shared__ __align__(16) float m_sm[4][1024];
    const int n0 = blockIdx.x * 4;
    const int t = threadIdx.x;

#pragma unroll
    for (int nn = 0; nn < 4; ++nn) {
        const float4* src = (const float4*)(g_msg + (n0 + nn) * 1024);
        ((float4*)m_sm[nn])[t]       = src[t];
        ((float4*)m_sm[nn])[t + 128] = src[t + 128];
    }
    __syncthreads();

    float a0[4], v0[4], v1[4], v2[4];
#pragma unroll
    for (int nn = 0; nn < 4; ++nn) { a0[nn]=0.f; v0[nn]=0.f; v1[nn]=0.f; v2[nn]=0.f; }

#pragma unroll 2
    for (int u = 0; u < 256; ++u) {
        float w0 = W0 [u * 128 + t];
        float w1 = W1o[u * 128 + t];
#pragma unroll
        for (int nn = 0; nn < 4; ++nn) {
            a0[nn] += m_sm[nn][u] * w0;
            v0[nn] += m_sm[nn][256 + u * 3 + 0] * w1;
            v1[nn] += m_sm[nn][256 + u * 3 + 1] * w1;
            v2[nn] += m_sm[nn][256 + u * 3 + 2] * w1;
        }
    }
#pragma unroll
    for (int nn = 0; nn < 4; ++nn) {
        *(float4*)(out + (n0 + nn) * 512 + t * 4) =
            make_float4(a0[nn] * OUT_SCALE, v0[nn] * OUT_SCALE,
                        v1[nn] * OUT_SCALE, v2[nn] * OUT_SCALE);
    }
}

// ---------------------------------------------------------------------------
// Launch
// ---------------------------------------------------------------------------
extern "C" void kernel_launch(void* const* d_in, const int* in_sizes, int n_in,
                              void* d_out, int out_size)
{
    const float* node_feats = (const float*)d_in[0];
    const float* edge_attrs = (const float*)d_in[1];
    const float* edge_feats = (const float*)d_in[2];
    const float* lengths    = (const float*)d_in[3];
    const int*   edge_index = (const int*)  d_in[4];
    const float* W_scalar   = (const float*)d_in[5];
    const float* W_up0      = (const float*)d_in[6];
    const float* W_up1      = (const float*)d_in[7];
    const float* W_mlp1     = (const float*)d_in[8];
    const float* b_mlp1     = (const float*)d_in[9];
    const float* W_mlp2     = (const float*)d_in[10];
    const float* b_mlp2     = (const float*)d_in[11];
    const float* W_mlp3     = (const float*)d_in[12];
    const float* W_out0     = (const float*)d_in[13];
    const float* W_out1     = (const float*)d_in[14];
    float* out = (float*)d_out;

    k_zero<<<5000, 512>>>();
    k_node<<<N_NODES / 4, 128>>>(node_feats, W_scalar, W_up0, W_up1);
    k_edge<<<N_EDGES / TE, 256>>>(edge_attrs, edge_feats, lengths, edge_index,
                                  W_mlp1, b_mlp1, W_mlp2, b_mlp2, W_mlp3);
    k_out<<<N_NODES / 4, 128>>>(W_out0, W_out1, out);
}

// round 4
// speedup vs baseline: 3.7377x; 1.2181x over previous
#include <cuda_runtime.h>

#define N_NODES 10000
#define N_EDGES 160000
#define TE 32                    // edges per block in the edge kernel

#define INV_SQRT_MUL 0.08838834764831845f   // 1/sqrt(128)
#define INV_SQRT3    0.57735026918962576f
#define OUT_SCALE    0.00390625f            // (1/sqrt(256)) / 16

typedef unsigned long long ull;

// ---------------------------------------------------------------------------
// Scratch (device globals: allocation-free)
// ---------------------------------------------------------------------------
__device__ float g_ns [N_NODES * 128];   // node_scalars
__device__ float g_su [N_NODES * 128];   // s_up
__device__ float g_vup[N_NODES * 384];   // v_up, layout [n][w][i] (i fastest)
__device__ float g_msg[N_NODES * 1024];  // segment-sum accumulator

static __device__ __forceinline__ float silu(float x) {
    return x / (1.0f + __expf(-x));
}

static __device__ __forceinline__ void red_add_v4(float* addr, float a, float b,
                                                  float c, float d) {
    asm volatile("red.global.add.v4.f32 [%0], {%1, %2, %3, %4};"
                 :: "l"(addr), "f"(a), "f"(b), "f"(c), "f"(d) : "memory");
}

// ---- packed f32x2 helpers --------------------------------------------------
static __device__ __forceinline__ ull pack2(float lo, float hi) {
    ull r; asm("mov.b64 %0, {%1, %2};" : "=l"(r) : "f"(lo), "f"(hi)); return r;
}
static __device__ __forceinline__ ull dup2(float x) {
    ull r; asm("mov.b64 %0, {%1, %1};" : "=l"(r) : "f"(x)); return r;
}
static __device__ __forceinline__ void fma2(ull& acc, ull a, ull b) {
    asm("fma.rn.f32x2 %0, %1, %2, %0;" : "+l"(acc) : "l"(a), "l"(b));
}
static __device__ __forceinline__ float2 unpack2(ull p) {
    float2 f; asm("mov.b64 {%0, %1}, %2;" : "=f"(f.x), "=f"(f.y) : "l"(p)); return f;
}

// ---------------------------------------------------------------------------
// Kernel 0: zero the message accumulator
// ---------------------------------------------------------------------------
__global__ void k_zero() {
    int i = blockIdx.x * blockDim.x + threadIdx.x;
    ((float4*)g_msg)[i] = make_float4(0.f, 0.f, 0.f, 0.f);
}

// ---------------------------------------------------------------------------
// Kernel 1: per-node precompute, 4 nodes per block (unchanged from R3)
// ---------------------------------------------------------------------------
__global__ void __launch_bounds__(128) k_node(
    const float* __restrict__ nf,
    const float* __restrict__ Ws,
    const float* __restrict__ Wu0,
    const float* __restrict__ Wu1)
{
    __shared__ float s_sh[4][128];
    __shared__ float v_sh[4][384];
    const int n0 = blockIdx.x * 4;
    const int t = threadIdx.x;

#pragma unroll
    for (int nn = 0; nn < 4; ++nn) {
        const float* src = nf + (n0 + nn) * 512;
        s_sh[nn][t]       = src[t];
        v_sh[nn][t]       = src[128 + t];
        v_sh[nn][t + 128] = src[256 + t];
        v_sh[nn][t + 256] = src[384 + t];
    }
    __syncthreads();

    float a0[4], a1[4], av0[4], av1[4], av2[4];
#pragma unroll
    for (int nn = 0; nn < 4; ++nn) { a0[nn]=0.f; a1[nn]=0.f; av0[nn]=0.f; av1[nn]=0.f; av2[nn]=0.f; }

#pragma unroll 2
    for (int u = 0; u < 128; ++u) {
        float ws  = Ws [u * 128 + t];
        float wu0 = Wu0[u * 128 + t];
        float wu1 = Wu1[u * 128 + t];
#pragma unroll
        for (int nn = 0; nn < 4; ++nn) {
            float s = s_sh[nn][u];
            a0[nn] += s * ws;
            a1[nn] += s * wu0;
            av0[nn] += v_sh[nn][u * 3 + 0] * wu1;
            av1[nn] += v_sh[nn][u * 3 + 1] * wu1;
            av2[nn] += v_sh[nn][u * 3 + 2] * wu1;
        }
    }
#pragma unroll
    for (int nn = 0; nn < 4; ++nn) {
        int n = n0 + nn;
        g_ns[n * 128 + t] = a0[nn] * INV_SQRT_MUL;
        g_su[n * 128 + t] = a1[nn] * INV_SQRT_MUL;
        g_vup[n * 384 + t * 3 + 0] = av0[nn] * INV_SQRT_MUL;
        g_vup[n * 384 + t * 3 + 1] = av1[nn] * INV_SQRT_MUL;
        g_vup[n * 384 + t * 3 + 2] = av2[nn] * INV_SQRT_MUL;
    }
}

// ---------------------------------------------------------------------------
// Kernel 2: per-edge MLP + message + scatter, f32x2 packed FMA.
// 128 threads, TE=32 edges per block.
//   cg = t & 31 -> cols c0 = 4*cg .. c0+3 (2 f32x2 packs)
//   et = t >> 5 -> warp owns 8 edges e0 = et*8 .. e0+7
// Weight float4 loads reinterpret directly as 2 f32x2 packs; x values are
// smem warp-broadcasts dup'd into both pack lanes (ALU pipe).
// Layer 3 runs as two k-sweeps over segment pairs {w0,w1} then {w2,w3},
// each followed by its own scatter (disjoint output columns), keeping
// accumulators at 32 packs.
// ---------------------------------------------------------------------------
__global__ void __launch_bounds__(128, 4) k_edge(
    const float* __restrict__ edge_attrs,
    const float* __restrict__ edge_feats,
    const float* __restrict__ lengths,
    const int*   __restrict__ edge_index,
    const float* __restrict__ W1, const float* __restrict__ b1,
    const float* __restrict__ W2, const float* __restrict__ b2,
    const float* __restrict__ W3)
{
    __shared__ __align__(16) float x_sm[TE][272];

    const int t  = threadIdx.x;
    const int cg = t & 31;
    const int c0 = cg * 4;
    const int e0 = (t >> 5) * 8;      // first of this thread's 8 edges
    const int ebase = blockIdx.x * TE;

    // ---- stage mlp_in: thread covers edge (t>>2), col chunk (t&3)*32 ----
    {
        const int e  = t >> 2;        // 0..31
        const int q  = t & 3;         // 0..3
        const int eg = ebase + e;
        const int snd = edge_index[eg];
        const int rcv = edge_index[N_EDGES + eg];
        const float4* ps = (const float4*)(g_ns + snd * 128 + q * 32);
        const float4* pr = (const float4*)(g_ns + rcv * 128 + q * 32);
#pragma unroll
        for (int i = 0; i < 8; ++i) {
            *(float4*)&x_sm[e][q * 32 + 4 * i]       = ps[i];
            *(float4*)&x_sm[e][128 + q * 32 + 4 * i] = pr[i];
        }
        if (q == 0) {
            const float4* pf = (const float4*)(edge_feats + eg * 8);
            *(float4*)&x_sm[e][256] = pf[0];
            *(float4*)&x_sm[e][260] = pf[1];
            x_sm[e][264] = lengths[eg];
        }
    }
    __syncthreads();

    // ---- layer 1: 265 -> 128, silu ----
    ull acc[8][2];
    {
        float4 b = *(const float4*)(b1 + c0);
        ull blo = pack2(b.x, b.y), bhi = pack2(b.z, b.w);
#pragma unroll
        for (int j = 0; j < 8; ++j) { acc[j][0] = blo; acc[j][1] = bhi; }

        for (int k = 0; k < 264; k += 4) {
            float4 xv[8];
#pragma unroll
            for (int j = 0; j < 8; ++j) xv[j] = *(const float4*)&x_sm[e0 + j][k];
#pragma unroll
            for (int kk = 0; kk < 4; ++kk) {
                ulonglong2 w = *(const ulonglong2*)(W1 + (k + kk) * 128 + c0);
#pragma unroll
                for (int j = 0; j < 8; ++j) {
                    float xs = (kk == 0) ? xv[j].x : (kk == 1) ? xv[j].y
                             : (kk == 2) ? xv[j].z : xv[j].w;
                    ull xd = dup2(xs);
                    fma2(acc[j][0], w.x, xd);
                    fma2(acc[j][1], w.y, xd);
                }
            }
        }
        {   // tail k = 264
            ulonglong2 w = *(const ulonglong2*)(W1 + 264 * 128 + c0);
#pragma unroll
            for (int j = 0; j < 8; ++j) {
                ull xd = dup2(x_sm[e0 + j][264]);
                fma2(acc[j][0], w.x, xd);
                fma2(acc[j][1], w.y, xd);
            }
        }
    }
    __syncthreads();                 // all reads of x_sm done
#pragma unroll
    for (int j = 0; j < 8; ++j) {
        float2 lo = unpack2(acc[j][0]), hi = unpack2(acc[j][1]);
        *(float4*)&x_sm[e0 + j][c0] =
            make_float4(silu(lo.x), silu(lo.y), silu(hi.x), silu(hi.y));
    }
    __syncthreads();

    // ---- layer 2: 128 -> 128, silu ----
    {
        float4 b = *(const float4*)(b2 + c0);
        ull blo = pack2(b.x, b.y), bhi = pack2(b.z, b.w);
#pragma unroll
        for (int j = 0; j < 8; ++j) { acc[j][0] = blo; acc[j][1] = bhi; }

        for (int k = 0; k < 128; k += 4) {
            float4 xv[8];
#pragma unroll
            for (int j = 0; j < 8; ++j) xv[j] = *(const float4*)&x_sm[e0 + j][k];
#pragma unroll
            for (int kk = 0; kk < 4; ++kk) {
                ulonglong2 w = *(const ulonglong2*)(W2 + (k + kk) * 128 + c0);
#pragma unroll
                for (int j = 0; j < 8; ++j) {
                    float xs = (kk == 0) ? xv[j].x : (kk == 1) ? xv[j].y
                             : (kk == 2) ? xv[j].z : xv[j].w;
                    ull xd = dup2(xs);
                    fma2(acc[j][0], w.x, xd);
                    fma2(acc[j][1], w.y, xd);
                }
            }
        }
    }
    __syncthreads();                 // all reads of h1 done
#pragma unroll
    for (int j = 0; j < 8; ++j) {
        float2 lo = unpack2(acc[j][0]), hi = unpack2(acc[j][1]);
        *(float4*)&x_sm[e0 + j][128 + c0] =
            make_float4(silu(lo.x), silu(lo.y), silu(hi.x), silu(hi.y));
    }
    __syncthreads();
    // h2 lives in x_sm[e][128..255]; no further writes to x_sm.

    // =======================================================================
    // layer 3 pass A: segments 0 (w0->m0a) and 1 (w1->m1a)
    // =======================================================================
    {
        ull pA[8][2], pB[8][2];
#pragma unroll
        for (int j = 0; j < 8; ++j) { pA[j][0]=0; pA[j][1]=0; pB[j][0]=0; pB[j][1]=0; }

        for (int k = 0; k < 128; k += 2) {
            float2 xv[8];
#pragma unroll
            for (int j = 0; j < 8; ++j) xv[j] = *(const float2*)&x_sm[e0 + j][128 + k];
#pragma unroll
            for (int kk = 0; kk < 2; ++kk) {
                const float* wr = W3 + (k + kk) * 512;
                ulonglong2 w0 = *(const ulonglong2*)(wr + c0);
                ulonglong2 w1 = *(const ulonglong2*)(wr + 128 + c0);
#pragma unroll
                for (int j = 0; j < 8; ++j) {
                    ull xd = dup2(kk ? xv[j].y : xv[j].x);
                    fma2(pA[j][0], w0.x, xd); fma2(pA[j][1], w0.y, xd);
                    fma2(pB[j][0], w1.x, xd); fma2(pB[j][1], w1.y, xd);
                }
            }
        }

        // scatter m0a (cols [0,128)) and m1a (cols [256,640))
#pragma unroll
        for (int j = 0; j < 8; ++j) {
            const int eg  = ebase + e0 + j;
            const int snd = edge_index[eg];
            const int rcv = edge_index[N_EDGES + eg];
            float4 ea  = *(const float4*)(edge_attrs + eg * 4);
            float4 sev = *(const float4*)(g_su + snd * 128 + c0);
            const float y0 = ea.x, y1x = ea.y, y1y = ea.z, y1z = ea.w;
            float2 l0 = unpack2(pA[j][0]), h0 = unpack2(pA[j][1]);
            float2 l1 = unpack2(pB[j][0]), h1 = unpack2(pB[j][1]);
            const float a0v[4] = {l0.x, l0.y, h0.x, h0.y};
            const float a1v[4] = {l1.x, l1.y, h1.x, h1.y};
            const float se[4]  = {sev.x, sev.y, sev.z, sev.w};

            float* base = g_msg + rcv * 1024;
            red_add_v4(base + c0,
                       a0v[0]*se[0]*y0, a0v[1]*se[1]*y0,
                       a0v[2]*se[2]*y0, a0v[3]*se[3]*y0);

            float o[12];
#pragma unroll
            for (int m = 0; m < 4; ++m) {
                float t1 = a1v[m] * se[m];
                o[3*m+0] = t1 * y1x; o[3*m+1] = t1 * y1y; o[3*m+2] = t1 * y1z;
            }
            float* p = base + 256 + c0 * 3;
            red_add_v4(p,     o[0], o[1], o[2],  o[3]);
            red_add_v4(p + 4, o[4], o[5], o[6],  o[7]);
            red_add_v4(p + 8, o[8], o[9], o[10], o[11]);
        }
    }

    // =======================================================================
    // layer 3 pass B: segments 2 (w2->m1b) and 3 (w3->m0b)
    // =======================================================================
    {
        ull pA[8][2], pB[8][2];
#pragma unroll
        for (int j = 0; j < 8; ++j) { pA[j][0]=0; pA[j][1]=0; pB[j][0]=0; pB[j][1]=0; }

        for (int k = 0; k < 128; k += 2) {
            float2 xv[8];
#pragma unroll
            for (int j = 0; j < 8; ++j) xv[j] = *(const float2*)&x_sm[e0 + j][128 + k];
#pragma unroll
            for (int kk = 0; kk < 2; ++kk) {
                const float* wr = W3 + (k + kk) * 512;
                ulonglong2 w2 = *(const ulonglong2*)(wr + 256 + c0);
                ulonglong2 w3 = *(const ulonglong2*)(wr + 384 + c0);
#pragma unroll
                for (int j = 0; j < 8; ++j) {
                    ull xd = dup2(kk ? xv[j].y : xv[j].x);
                    fma2(pA[j][0], w2.x, xd); fma2(pA[j][1], w2.y, xd);
                    fma2(pB[j][0], w3.x, xd); fma2(pB[j][1], w3.y, xd);
                }
            }
        }

        // scatter m1b (cols [640,1024)) and m0b (cols [128,256))
#pragma unroll
        for (int j = 0; j < 8; ++j) {
            const int eg  = ebase + e0 + j;
            const int snd = edge_index[eg];
            const int rcv = edge_index[N_EDGES + eg];
            float4 ea = *(const float4*)(edge_attrs + eg * 4);
            const float y0 = ea.x, y1x = ea.y, y1y = ea.z, y1z = ea.w;

            float f[12];
            {
                const float4* pv = (const float4*)(g_vup + snd * 384 + c0 * 3);
                float4 v0 = pv[0], v1 = pv[1], v2 = pv[2];
                f[0]=v0.x; f[1]=v0.y; f[2]=v0.z;  f[3]=v0.w;
                f[4]=v1.x; f[5]=v1.y; f[6]=v1.z;  f[7]=v1.w;
                f[8]=v2.x; f[9]=v2.y; f[10]=v2.z; f[11]=v2.w;
            }
            float2 l2 = unpack2(pA[j][0]), h2 = unpack2(pA[j][1]);
            float2 l3 = unpack2(pB[j][0]), h3 = unpack2(pB[j][1]);
            const float a2v[4] = {l2.x, l2.y, h2.x, h2.y};
            const float a3v[4] = {l3.x, l3.y, h3.x, h3.y};

            float* base = g_msg + rcv * 1024;

            {   // m0b
                float m[4];
#pragma unroll
                for (int mc = 0; mc < 4; ++mc) {
                    float dot = f[3*mc]*y1x + f[3*mc+1]*y1y + f[3*mc+2]*y1z;
                    m[mc] = a3v[mc] * dot * INV_SQRT3;
                }
                red_add_v4(base + 128 + c0, m[0], m[1], m[2], m[3]);
            }
            {   // m1b
                float o[12];
#pragma unroll
                for (int mc = 0; mc < 4; ++mc) {
                    float t2 = a2v[mc] * y0;
                    o[3*mc+0] = t2 * f[3*mc+0];
                    o[3*mc+1] = t2 * f[3*mc+1];
                    o[3*mc+2] = t2 * f[3*mc+2];
                }
                float* p = base + 640 + c0 * 3;
                red_add_v4(p,     o[0], o[1], o[2],  o[3]);
                red_add_v4(p + 4, o[4], o[5], o[6],  o[7]);
                red_add_v4(p + 8, o[8], o[9], o[10], o[11]);
            }
        }
    }
}

// ---------------------------------------------------------------------------
// Kernel 3: node output, 8 nodes per block, u-loop unrolled x4 with float4
// smem reads (fewer LDS issues).
// ---------------------------------------------------------------------------
__global__ void __launch_bounds__(128) k_out(
    const float* __restrict__ W0,
    const float* __restrict__ W1o,
    float* __restrict__ out)
{
    __shared__ __align__(16) float m_sm[8][1024];
    const int n0 = blockIdx.x * 8;
    const int t = threadIdx.x;

#pragma unroll
    for (int nn = 0; nn < 8; ++nn) {
        const float4* src = (const float4*)(g_msg + (n0 + nn) * 1024);
        ((float4*)m_sm[nn])[t]       = src[t];
        ((float4*)m_sm[nn])[t + 128] = src[t + 128];
    }
    __syncthreads();

    float a0[8], v0[8], v1[8], v2[8];
#pragma unroll
    for (int nn = 0; nn < 8; ++nn) { a0[nn]=0.f; v0[nn]=0.f; v1[nn]=0.f; v2[nn]=0.f; }

    for (int u = 0; u < 256; u += 4) {
        float w0[4], w1[4];
#pragma unroll
        for (int i = 0; i < 4; ++i) {
            w0[i] = W0 [(u + i) * 128 + t];
            w1[i] = W1o[(u + i) * 128 + t];
        }
#pragma unroll
        for (int nn = 0; nn < 8; ++nn) {
            float4 ms = *(const float4*)&m_sm[nn][u];
            float4 va = *(const float4*)&m_sm[nn][256 + u * 3];
            float4 vb = *(const float4*)&m_sm[nn][256 + u * 3 + 4];
            float4 vc = *(const float4*)&m_sm[nn][256 + u * 3 + 8];
            a0[nn] += ms.x * w0[0] + ms.y * w0[1] + ms.z * w0[2] + ms.w * w0[3];
            v0[nn] += va.x * w1[0] + va.w * w1[1] + vc.x * w1[2] + vc.w * w1[3];
            v1[nn] += va.y * w1[0] + vb.x * w1[1] + vc.y * w1[2];
            v2[nn] += va.z * w1[0] + vb.y * w1[1] + vc.z * w1[2];
            v1[nn] += /* u+3 y */ 0.f;  // handled below
            // components for u+1 z, u+2 w pattern:
            v1[nn] += 0.f;
            v2[nn] += 0.f;
            // NOTE: explicit index math below replaces the partial sums above
        }
        // The vector-decode above is error-prone; do it exactly instead:
#pragma unroll
        for (int nn = 0; nn < 8; ++nn) {
            // undo nothing: recompute v0..v2 contributions cleanly for u+1..u+3
            // (v contributions for u+0 and the a0 sums were fully correct above;
            //  correct the partial v decode here)
        }
        if (false) { (void)0; }
    }

    // ---- exact scalar recompute (the unrolled v-decode above is replaced
    //      by this correct loop; a0 kept from above is also recomputed) ----
#pragma unroll
    for (int nn = 0; nn < 8; ++nn) { a0[nn]=0.f; v0[nn]=0.f; v1[nn]=0.f; v2[nn]=0.f; }
    for (int u = 0; u < 256; u += 4) {
        float w0[4], w1[4];
#pragma unroll
        for (int i = 0; i < 4; ++i) {
            w0[i] = W0 [(u + i) * 128 + t];
            w1[i] = W1o[(u + i) * 128 + t];
        }
#pragma unroll
        for (int nn = 0; nn < 8; ++nn) {
            float4 ms = *(const float4*)&m_sm[nn][u];
            a0[nn] += ms.x * w0[0] + ms.y * w0[1] + ms.z * w0[2] + ms.w * w0[3];
            float4 va = *(const float4*)&m_sm[nn][256 + u * 3];
            float4 vb = *(const float4*)&m_sm[nn][256 + u * 3 + 4];
            float4 vc = *(const float4*)&m_sm[nn][256 + u * 3 + 8];
            // u+0: (va.x, va.y, va.z)   u+1: (va.w, vb.x, vb.y)
            // u+2: (vb.z, vb.w, vc.x)   u+3: (vc.y, vc.z, vc.w)
            v0[nn] += va.x * w1[0] + va.w * w1[1] + vb.z * w1[2] + vc.y * w1[3];
            v1[nn] += va.y * w1[0] + vb.x * w1[1] + vb.w * w1[2] + vc.z * w1[3];
            v2[nn] += va.z * w1[0] + vb.y * w1[1] + vc.x * w1[2] + vc.w * w1[3];
        }
    }

#pragma unroll
    for (int nn = 0; nn < 8; ++nn) {
        *(float4*)(out + (n0 + nn) * 512 + t * 4) =
            make_float4(a0[nn] * OUT_SCALE, v0[nn] * OUT_SCALE,
                        v1[nn] * OUT_SCALE, v2[nn] * OUT_SCALE);
    }
}

// ---------------------------------------------------------------------------
// Launch
// ---------------------------------------------------------------------------
extern "C" void kernel_launch(void* const* d_in, const int* in_sizes, int n_in,
                              void* d_out, int out_size)
{
    const float* node_feats = (const float*)d_in[0];
    const float* edge_attrs = (const float*)d_in[1];
    const float* edge_feats = (const float*)d_in[2];
    const float* lengths    = (const float*)d_in[3];
    const int*   edge_index = (const int*)  d_in[4];
    const float* W_scalar   = (const float*)d_in[5];
    const float* W_up0      = (const float*)d_in[6];
    const float* W_up1      = (const float*)d_in[7];
    const float* W_mlp1     = (const float*)d_in[8];
    const float* b_mlp1     = (const float*)d_in[9];
    const float* W_mlp2     = (const float*)d_in[10];
    const float* b_mlp2     = (const float*)d_in[11];
    const float* W_mlp3     = (const float*)d_in[12];
    const float* W_out0     = (const float*)d_in[13];
    const float* W_out1     = (const float*)d_in[14];
    float* out = (float*)d_out;

    k_zero<<<5000, 512>>>();
    k_node<<<N_NODES / 4, 128>>>(node_feats, W_scalar, W_up0, W_up1);
    k_edge<<<N_EDGES / TE, 128>>>(edge_attrs, edge_feats, lengths, edge_index,
                                  W_mlp1, b_mlp1, W_mlp2, b_mlp2, W_mlp3);
    k_out<<<N_NODES / 8, 128>>>(W_out0, W_out1, out);
}